// round 5
// baseline (speedup 1.0000x reference)
#include <cuda_runtime.h>
#include <cuda_bf16.h>
#include <math.h>
#include <stdint.h>

#define BB 32
#define NN 512
#define HH 128

// h split-bf16 planes, [b][d][n] (transposed), row-contiguous in n. 4 MB each.
__device__ __nv_bfloat16 g_hBhi[BB * HH * NN];
__device__ __nv_bfloat16 g_hBlo[BB * HH * NN];

__device__ __forceinline__ uint32_t smem_u32(const void* p) {
    uint32_t a;
    asm("{ .reg .u64 t; cvta.to.shared.u64 t, %1; cvt.u32.u64 %0, t; }"
        : "=r"(a) : "l"(p));
    return a;
}

#define CP_ASYNC16(dst_u32, src_ptr) \
    asm volatile("cp.async.cg.shared.global [%0], [%1], 16;" \
                 :: "r"(dst_u32), "l"(src_ptr) : "memory")
#define CP_COMMIT() asm volatile("cp.async.commit_group;" ::: "memory")
#define CP_WAIT(n)  asm volatile("cp.async.wait_group %0;" :: "n"(n) : "memory")

// ---------------------------------------------------------------------------
// K1: h = silu(LN(s @ W1^T + b1)); writes transposed split-bf16 planes.
// ---------------------------------------------------------------------------
__global__ void __launch_bounds__(256)
k1_lin_ln_silu(const float* __restrict__ s,
               const float* __restrict__ W1,
               const float* __restrict__ b1) {
    extern __shared__ float smem[];
    float*    W1T = smem;                           // 128*132 floats
    float*    sT  = smem + 128 * 132;               // 128*33 floats (reused as hp)
    uint32_t* tr  = (uint32_t*)(smem + 128 * 132 + 128 * 33);  // 128*33 u32

    const int t    = threadIdx.x;
    const int row0 = blockIdx.x * 32;

#pragma unroll 8
    for (int k = 0; k < 64; ++k) {
        int u = t + k * 256;
        int c = u >> 7, h = u & 127;
        W1T[h * 132 + c] = W1[u];
    }
#pragma unroll 8
    for (int k = 0; k < 16; ++k) {
        int u = t + k * 256;
        int r = u >> 7, h = u & 127;
        sT[h * 33 + r] = s[row0 * 128 + u];
    }
    __syncthreads();

    const int cg = t & 31;
    const int rg = t >> 5;

    float4 acc0 = make_float4(0.f, 0.f, 0.f, 0.f);
    float4 acc1 = acc0, acc2 = acc0, acc3 = acc0;

    const float4* W1T4 = (const float4*)W1T;
#pragma unroll 4
    for (int h = 0; h < 128; ++h) {
        float4 w = W1T4[h * 33 + cg];
        float a0 = sT[h * 33 + rg * 4 + 0];
        float a1 = sT[h * 33 + rg * 4 + 1];
        float a2 = sT[h * 33 + rg * 4 + 2];
        float a3 = sT[h * 33 + rg * 4 + 3];
        acc0.x += a0 * w.x; acc0.y += a0 * w.y; acc0.z += a0 * w.z; acc0.w += a0 * w.w;
        acc1.x += a1 * w.x; acc1.y += a1 * w.y; acc1.z += a1 * w.z; acc1.w += a1 * w.w;
        acc2.x += a2 * w.x; acc2.y += a2 * w.y; acc2.z += a2 * w.z; acc2.w += a2 * w.w;
        acc3.x += a3 * w.x; acc3.y += a3 * w.y; acc3.z += a3 * w.z; acc3.w += a3 * w.w;
    }
    {
        float4 bv = ((const float4*)b1)[cg];
        acc0.x += bv.x; acc0.y += bv.y; acc0.z += bv.z; acc0.w += bv.w;
        acc1.x += bv.x; acc1.y += bv.y; acc1.z += bv.z; acc1.w += bv.w;
        acc2.x += bv.x; acc2.y += bv.y; acc2.z += bv.z; acc2.w += bv.w;
        acc3.x += bv.x; acc3.y += bv.y; acc3.z += bv.z; acc3.w += bv.w;
    }

    __syncthreads();
    float4* hp4 = (float4*)sT;    // [32 rows][32 float4]
    hp4[(rg * 4 + 0) * 32 + cg] = acc0;
    hp4[(rg * 4 + 1) * 32 + cg] = acc1;
    hp4[(rg * 4 + 2) * 32 + cg] = acc2;
    hp4[(rg * 4 + 3) * 32 + cg] = acc3;
    __syncthreads();

    const float inv128 = 1.0f / 128.0f;
#pragma unroll
    for (int rr = 0; rr < 4; ++rr) {
        int row = rg * 4 + rr;
        float4 x = hp4[row * 32 + cg];
        float sm = x.x + x.y + x.z + x.w;
        float sq = x.x * x.x + x.y * x.y + x.z * x.z + x.w * x.w;
#pragma unroll
        for (int o = 16; o > 0; o >>= 1) {
            sm += __shfl_xor_sync(0xFFFFFFFFu, sm, o);
            sq += __shfl_xor_sync(0xFFFFFFFFu, sq, o);
        }
        float mu  = sm * inv128;
        float var = sq * inv128 - mu * mu;
        float rs  = rsqrtf(var + 1e-5f);
        float y[4];
        y[0] = (x.x - mu) * rs; y[1] = (x.y - mu) * rs;
        y[2] = (x.z - mu) * rs; y[3] = (x.w - mu) * rs;
#pragma unroll
        for (int q = 0; q < 4; ++q) {
            float yv = y[q] / (1.0f + __expf(-y[q]));    // silu
            __nv_bfloat16 hi = __float2bfloat16(yv);
            __nv_bfloat16 lo = __float2bfloat16(yv - __bfloat162float(hi));
            uint32_t pk = (uint32_t)__bfloat16_as_ushort(hi)
                        | ((uint32_t)__bfloat16_as_ushort(lo) << 16);
            tr[(4 * cg + q) * 33 + row] = pk;
        }
    }
    __syncthreads();

    // store split planes: pairs of consecutive n packed into u32
    const int b  = row0 >> 9;
    const int n0 = row0 & 511;
#pragma unroll
    for (int k = 0; k < 8; ++k) {
        int u = t + k * 256;              // 0..2047
        int d = u >> 4, np = u & 15;
        uint32_t t0 = tr[d * 33 + 2 * np];
        uint32_t t1 = tr[d * 33 + 2 * np + 1];
        uint32_t hip = (t0 & 0xFFFFu) | (t1 << 16);
        uint32_t lop = (t0 >> 16) | (t1 & 0xFFFF0000u);
        int idx = ((b * 128 + d) * 512 + n0) / 2 + np;
        ((uint32_t*)g_hBhi)[idx] = hip;
        ((uint32_t*)g_hBlo)[idx] = lop;
    }
}

// ---------------------------------------------------------------------------
// K2: pipelined split-bf16 HMMA CFConv.
// grid: 32 b x 8 i-tiles (64 i) = 256 CTAs, 512 threads (16 warps 4m x 4n).
// smem: conv A [c][split][64 i][144B]   (55296 B)
//       conv B [split][128 d][144B]     @55296  (36864 B)
//       raw ev [64 i][768B]             @92160  (49152 B)
//       raw mk [64 i][256B]             @141312 (16384 B)
// cp.async pipeline: EM(ch+1) in flight under MMA(ch); B(ch) under convert(ch).
// NOTE: barrier between convert-A (cross-thread RAW_MK reads) and issue_EM
// (RAW_MK overwrite) — removing it races and corrupts the mask (R4 bug).
// ---------------------------------------------------------------------------
#define A_C_STRIDE   18432
#define A_S_STRIDE   9216
#define SM_ROW       144
#define B_BASE       55296
#define B_S_STRIDE   18432
#define RAW_EV       92160
#define RAW_MK       141312
#define K2_SMEM      157696

#define LDSM_X4(r, addr) \
    asm volatile("ldmatrix.sync.aligned.m8n8.x4.shared.b16 {%0,%1,%2,%3}, [%4];" \
                 : "=r"((r)[0]), "=r"((r)[1]), "=r"((r)[2]), "=r"((r)[3]) \
                 : "r"(addr))

#define MMA_BF16(acc, a, b0, b1) \
    asm volatile("mma.sync.aligned.m16n8k16.row.col.f32.bf16.bf16.f32 " \
                 "{%0,%1,%2,%3}, {%4,%5,%6,%7}, {%8,%9}, {%0,%1,%2,%3};" \
                 : "+f"((acc)[0]), "+f"((acc)[1]), "+f"((acc)[2]), "+f"((acc)[3]) \
                 : "r"((a)[0]), "r"((a)[1]), "r"((a)[2]), "r"((a)[3]), \
                   "r"(b0), "r"(b1))

__global__ void __launch_bounds__(512, 1)
k2_cfconv_mma(const float* __restrict__ ev,
              const float* __restrict__ mask,
              float* __restrict__ out) {
    extern __shared__ char smc[];
    const uint32_t smem_base = smem_u32(smc);
    const int t    = threadIdx.x;
    const int lane = t & 31;
    const int wid  = t >> 5;
    const int wm   = wid >> 2;     // 0..3: i-subtile of 16
    const int wn   = wid & 3;      // 0..3: d-subtile of 32
    const int b    = blockIdx.x >> 3;
    const int i0   = (blockIdx.x & 7) * 64;

    float acc[3][4][4];
#pragma unroll
    for (int c = 0; c < 3; ++c)
#pragma unroll
        for (int nt = 0; nt < 4; ++nt)
#pragma unroll
            for (int q = 0; q < 4; ++q) acc[c][nt][q] = 0.0f;

    const uint32_t a_lane = (uint32_t)((wm * 16 + (lane & 15)) * SM_ROW + (lane >> 4) * 16);
    uint32_t b_lane[2];
#pragma unroll
    for (int q = 0; q < 2; ++q) {
        int n = wn * 32 + q * 16 + (lane & 7) + ((lane >> 4) & 1) * 8;
        b_lane[q] = (uint32_t)(B_BASE + n * SM_ROW + ((lane >> 3) & 1) * 16);
    }

    // ---- cp.async issue helpers (each thread owns fixed chunk set)
    auto issue_EM = [&](int j0) {
        // ev: 64 i rows x 768B = 3072 16B-chunks
#pragma unroll
        for (int p = t; p < 3072; p += 512) {
            int i = p / 48, q = p - i * 48;
            const char* src = (const char*)ev
                + ((size_t)((b * 512 + i0 + i) * 512 + j0) * 12) + q * 16;
            CP_ASYNC16(smem_base + RAW_EV + i * 768 + q * 16, src);
        }
        // mask: 64 i rows x 256B = 1024 chunks
#pragma unroll
        for (int p = t; p < 1024; p += 512) {
            int i = p >> 4, q = p & 15;
            const char* src = (const char*)mask
                + ((size_t)((b * 512 + i0 + i) * 512 + j0) * 4) + q * 16;
            CP_ASYNC16(smem_base + RAW_MK + i * 256 + q * 16, src);
        }
        CP_COMMIT();
    };
    auto issue_B = [&](int j0) {
        // 2 splits x 128 d rows x 128B = 2048 chunks
#pragma unroll
        for (int p = t; p < 2048; p += 512) {
            int sp = p >> 10, r = p & 1023;
            int d = r >> 3, q = r & 7;
            const char* srcbase = sp ? (const char*)g_hBlo : (const char*)g_hBhi;
            const char* src = srcbase + ((size_t)((b * 128 + d) * 512 + j0) * 2) + q * 16;
            CP_ASYNC16(smem_base + B_BASE + sp * B_S_STRIDE + d * SM_ROW + q * 16, src);
        }
        CP_COMMIT();
    };

    issue_EM(0);       // prologue: EM(0) in flight

    for (int ch = 0; ch < 8; ++ch) {
        const int j0 = ch * 64;
        __syncthreads();            // MMA(ch-1) done -> conv buffers free
        issue_B(j0);                // B(ch): global -> conv B directly
        CP_WAIT(1);                 // own EM(ch) done (B may pend)
        __syncthreads();            // all EM(ch) visible

        // ---- convert A: raw ev * raw mask -> split bf16 conv A
#pragma unroll
        for (int p = t; p < 3072; p += 512) {
            int i   = p / 48;
            int rem = p - i * 48;
            float4 e4 = ((const float4*)(smc + RAW_EV + i * 768))[rem];
            const float* ep = &e4.x;
#pragma unroll
            for (int q = 0; q < 4; ++q) {
                int l = rem * 4 + q;            // 0..191
                int j = (l * 171) >> 9;         // l / 3
                int c = l - 3 * j;
                float m = *(const float*)(smc + RAW_MK + i * 256 + j * 4);
                float v = ep[q] * m;
                uint32_t vb  = __float_as_uint(v);
                uint32_t hib = vb & 0xFFFF0000u;
                float    lo  = v - __uint_as_float(hib);
                uint16_t lo16 = __bfloat16_as_ushort(__float2bfloat16(lo));
                char* base = smc + c * A_C_STRIDE + i * SM_ROW + j * 2;
                *(uint16_t*)(base)              = (uint16_t)(vb >> 16);
                *(uint16_t*)(base + A_S_STRIDE) = lo16;
            }
        }
        __syncthreads();            // ALL convert reads of RAW done before overwrite
                                    // (this barrier was missing in R4 -> mask race)

        if (ch < 7) { issue_EM(j0 + 64); CP_WAIT(1); }   // EM(ch+1) pends; B done
        else        { CP_WAIT(0); }
        __syncthreads();            // conv A STS + all B visible

        // ---- compute: 4 k16-steps x 3c x 4nt x 3 passes
#pragma unroll
        for (int kb = 0; kb < 4; ++kb) {
            uint32_t afr[3][2][4];
            uint32_t bfr[2][2][4];
#pragma unroll
            for (int c = 0; c < 3; ++c)
#pragma unroll
                for (int s = 0; s < 2; ++s)
                    LDSM_X4(afr[c][s],
                            smem_base + c * A_C_STRIDE + s * A_S_STRIDE + a_lane + kb * 32);
#pragma unroll
            for (int s = 0; s < 2; ++s)
#pragma unroll
                for (int q = 0; q < 2; ++q)
                    LDSM_X4(bfr[s][q], smem_base + b_lane[q] + s * B_S_STRIDE + kb * 32);

#pragma unroll
            for (int c = 0; c < 3; ++c) {
#pragma unroll
                for (int nt = 0; nt < 4; ++nt) {
                    uint32_t* bh = bfr[0][nt >> 1];
                    uint32_t* bl = bfr[1][nt >> 1];
                    uint32_t b0h = bh[(nt & 1) * 2], b1h = bh[(nt & 1) * 2 + 1];
                    uint32_t b0l = bl[(nt & 1) * 2], b1l = bl[(nt & 1) * 2 + 1];
                    MMA_BF16(acc[c][nt], afr[c][0], b0h, b1h);   // hi * hi
                    MMA_BF16(acc[c][nt], afr[c][1], b0h, b1h);   // lo * hi
                    MMA_BF16(acc[c][nt], afr[c][0], b0l, b1l);   // hi * lo
                }
            }
        }
    }

    // ---- epilogue: fragments -> out[b][i][c][d]
    const int r0 = i0 + wm * 16 + (lane >> 2);
    const int dq = wn * 32 + (lane & 3) * 2;
#pragma unroll
    for (int c = 0; c < 3; ++c) {
#pragma unroll
        for (int nt = 0; nt < 4; ++nt) {
            int d = dq + nt * 8;
            size_t o0 = ((size_t)(b * 512 + r0)     * 3 + c) * 128 + d;
            size_t o1 = ((size_t)(b * 512 + r0 + 8) * 3 + c) * 128 + d;
            *(float2*)(out + o0) = make_float2(acc[c][nt][0], acc[c][nt][1]);
            *(float2*)(out + o1) = make_float2(acc[c][nt][2], acc[c][nt][3]);
        }
    }
}

// ---------------------------------------------------------------------------
extern "C" void kernel_launch(void* const* d_in, const int* in_sizes, int n_in,
                              void* d_out, int out_size) {
    const float* s    = (const float*)d_in[0];   // (32,512,128)
    const float* ev   = (const float*)d_in[1];   // (32,512,512,3)
    const float* mask = (const float*)d_in[2];   // (32,512,512,1)
    const float* W1   = (const float*)d_in[3];   // (128,128)
    const float* b1   = (const float*)d_in[4];   // (128,)
    float* out = (float*)d_out;                  // (32,512,3,128)

    const int k1_smem = (128 * 132 + 128 * 33) * (int)sizeof(float)
                      + 128 * 33 * (int)sizeof(uint32_t);   // 101376
    cudaFuncSetAttribute(k1_lin_ln_silu,
                         cudaFuncAttributeMaxDynamicSharedMemorySize, k1_smem);
    cudaFuncSetAttribute(k2_cfconv_mma,
                         cudaFuncAttributeMaxDynamicSharedMemorySize, K2_SMEM);

    k1_lin_ln_silu<<<(BB * NN) / 32, 256, k1_smem>>>(s, W1, b1);
    k2_cfconv_mma<<<BB * 8, 512, K2_SMEM>>>(ev, mask, out);
}

// round 6
// speedup vs baseline: 1.1650x; 1.1650x over previous
#include <cuda_runtime.h>
#include <cuda_bf16.h>
#include <math.h>
#include <stdint.h>

#define BB 32
#define NN 512
#define HH 128

// h split-bf16 planes, [b][d][n] (transposed), row-contiguous in n. 4 MB each.
__device__ __nv_bfloat16 g_hBhi[BB * HH * NN];
__device__ __nv_bfloat16 g_hBlo[BB * HH * NN];

__device__ __forceinline__ uint32_t smem_u32(const void* p) {
    uint32_t a;
    asm("{ .reg .u64 t; cvta.to.shared.u64 t, %1; cvt.u32.u64 %0, t; }"
        : "=r"(a) : "l"(p));
    return a;
}

#define CP_ASYNC16(dst_u32, src_ptr) \
    asm volatile("cp.async.cg.shared.global [%0], [%1], 16;" \
                 :: "r"(dst_u32), "l"(src_ptr) : "memory")
#define CP_COMMIT() asm volatile("cp.async.commit_group;" ::: "memory")
#define CP_WAIT(n)  asm volatile("cp.async.wait_group %0;" :: "n"(n) : "memory")

// ---------------------------------------------------------------------------
// K1: h = silu(LN(s @ W1^T + b1)); writes transposed split-bf16 planes.
// 256 CTAs x 256 thr; each CTA: 64 rows as two 32-row tiles, W1T loaded once.
// ---------------------------------------------------------------------------
__global__ void __launch_bounds__(256)
k1_lin_ln_silu(const float* __restrict__ s,
               const float* __restrict__ W1,
               const float* __restrict__ b1) {
    extern __shared__ float smem[];
    float*    W1T = smem;                           // 128*132 floats
    float*    sT  = smem + 128 * 132;               // 128*33 floats (reused as hp)
    uint32_t* tr  = (uint32_t*)(smem + 128 * 132 + 128 * 33);  // 128*33 u32

    const int t    = threadIdx.x;
    const int row0 = blockIdx.x * 64;
    const int cg = t & 31;
    const int rg = t >> 5;

#pragma unroll 8
    for (int k = 0; k < 64; ++k) {
        int u = t + k * 256;
        int c = u >> 7, h = u & 127;
        W1T[h * 132 + c] = W1[u];
    }

    for (int rt = 0; rt < 2; ++rt) {
        const int rbase = row0 + rt * 32;
        __syncthreads();          // prev tile fully consumed (tr stored, hp read)
#pragma unroll 8
        for (int k = 0; k < 16; ++k) {
            int u = t + k * 256;
            int r = u >> 7, h = u & 127;
            sT[h * 33 + r] = s[rbase * 128 + u];
        }
        __syncthreads();

        float4 acc0 = make_float4(0.f, 0.f, 0.f, 0.f);
        float4 acc1 = acc0, acc2 = acc0, acc3 = acc0;

        const float4* W1T4 = (const float4*)W1T;
#pragma unroll 4
        for (int h = 0; h < 128; ++h) {
            float4 w = W1T4[h * 33 + cg];
            float a0 = sT[h * 33 + rg * 4 + 0];
            float a1 = sT[h * 33 + rg * 4 + 1];
            float a2 = sT[h * 33 + rg * 4 + 2];
            float a3 = sT[h * 33 + rg * 4 + 3];
            acc0.x += a0 * w.x; acc0.y += a0 * w.y; acc0.z += a0 * w.z; acc0.w += a0 * w.w;
            acc1.x += a1 * w.x; acc1.y += a1 * w.y; acc1.z += a1 * w.z; acc1.w += a1 * w.w;
            acc2.x += a2 * w.x; acc2.y += a2 * w.y; acc2.z += a2 * w.z; acc2.w += a2 * w.w;
            acc3.x += a3 * w.x; acc3.y += a3 * w.y; acc3.z += a3 * w.z; acc3.w += a3 * w.w;
        }
        {
            float4 bv = ((const float4*)b1)[cg];
            acc0.x += bv.x; acc0.y += bv.y; acc0.z += bv.z; acc0.w += bv.w;
            acc1.x += bv.x; acc1.y += bv.y; acc1.z += bv.z; acc1.w += bv.w;
            acc2.x += bv.x; acc2.y += bv.y; acc2.z += bv.z; acc2.w += bv.w;
            acc3.x += bv.x; acc3.y += bv.y; acc3.z += bv.z; acc3.w += bv.w;
        }

        __syncthreads();          // sT reads done -> reuse as hp
        float4* hp4 = (float4*)sT;    // [32 rows][32 float4]
        hp4[(rg * 4 + 0) * 32 + cg] = acc0;
        hp4[(rg * 4 + 1) * 32 + cg] = acc1;
        hp4[(rg * 4 + 2) * 32 + cg] = acc2;
        hp4[(rg * 4 + 3) * 32 + cg] = acc3;
        __syncthreads();

        const float inv128 = 1.0f / 128.0f;
#pragma unroll
        for (int rr = 0; rr < 4; ++rr) {
            int row = rg * 4 + rr;
            float4 x = hp4[row * 32 + cg];
            float sm = x.x + x.y + x.z + x.w;
            float sq = x.x * x.x + x.y * x.y + x.z * x.z + x.w * x.w;
#pragma unroll
            for (int o = 16; o > 0; o >>= 1) {
                sm += __shfl_xor_sync(0xFFFFFFFFu, sm, o);
                sq += __shfl_xor_sync(0xFFFFFFFFu, sq, o);
            }
            float mu  = sm * inv128;
            float var = sq * inv128 - mu * mu;
            float rs  = rsqrtf(var + 1e-5f);
            float y[4];
            y[0] = (x.x - mu) * rs; y[1] = (x.y - mu) * rs;
            y[2] = (x.z - mu) * rs; y[3] = (x.w - mu) * rs;
#pragma unroll
            for (int q = 0; q < 4; ++q) {
                float yv = y[q] / (1.0f + __expf(-y[q]));    // silu
                __nv_bfloat16 hi = __float2bfloat16(yv);
                __nv_bfloat16 lo = __float2bfloat16(yv - __bfloat162float(hi));
                uint32_t pk = (uint32_t)__bfloat16_as_ushort(hi)
                            | ((uint32_t)__bfloat16_as_ushort(lo) << 16);
                tr[(4 * cg + q) * 33 + row] = pk;
            }
        }
        __syncthreads();

        // store split planes: pairs of consecutive n packed into u32
        const int b  = row0 >> 9;
        const int n0 = (row0 & 511) + rt * 32;
#pragma unroll
        for (int k = 0; k < 8; ++k) {
            int u = t + k * 256;              // 0..2047
            int d = u >> 4, np = u & 15;
            uint32_t t0 = tr[d * 33 + 2 * np];
            uint32_t t1 = tr[d * 33 + 2 * np + 1];
            uint32_t hip = (t0 & 0xFFFFu) | (t1 << 16);
            uint32_t lop = (t0 >> 16) | (t1 & 0xFFFF0000u);
            int idx = ((b * 128 + d) * 512 + n0) / 2 + np;
            ((uint32_t*)g_hBhi)[idx] = hip;
            ((uint32_t*)g_hBlo)[idx] = lop;
        }
    }
}

// ---------------------------------------------------------------------------
// K2: pipelined split-bf16 HMMA CFConv.
// grid: 32 b x 8 i-tiles (64 i) = 256 CTAs, 512 threads (16 warps 4m x 4n).
// smem: conv A [c][split][64 i][144B]   (55296 B)
//       conv B [split][128 d][144B]     @55296  (36864 B)
//       raw ev [64 i][768B]             @92160  (49152 B)
//       raw mk [64 i][256B]             @141312 (16384 B)
// Convert: per-thread blocks of (i,c, 8 consecutive j) -> packed STS.128.
// MMA: pass-major order (12 indep MMAs between same-acc touches).
// ---------------------------------------------------------------------------
#define A_C_STRIDE   18432
#define A_S_STRIDE   9216
#define SM_ROW       144
#define B_BASE       55296
#define B_S_STRIDE   18432
#define RAW_EV       92160
#define RAW_MK       141312
#define K2_SMEM      157696

#define LDSM_X4(r, addr) \
    asm volatile("ldmatrix.sync.aligned.m8n8.x4.shared.b16 {%0,%1,%2,%3}, [%4];" \
                 : "=r"((r)[0]), "=r"((r)[1]), "=r"((r)[2]), "=r"((r)[3]) \
                 : "r"(addr))

#define MMA_BF16(acc, a, b0, b1) \
    asm volatile("mma.sync.aligned.m16n8k16.row.col.f32.bf16.bf16.f32 " \
                 "{%0,%1,%2,%3}, {%4,%5,%6,%7}, {%8,%9}, {%0,%1,%2,%3};" \
                 : "+f"((acc)[0]), "+f"((acc)[1]), "+f"((acc)[2]), "+f"((acc)[3]) \
                 : "r"((a)[0]), "r"((a)[1]), "r"((a)[2]), "r"((a)[3]), \
                   "r"(b0), "r"(b1))

__global__ void __launch_bounds__(512, 1)
k2_cfconv_mma(const float* __restrict__ ev,
              const float* __restrict__ mask,
              float* __restrict__ out) {
    extern __shared__ char smc[];
    const uint32_t smem_base = smem_u32(smc);
    const int t    = threadIdx.x;
    const int lane = t & 31;
    const int wid  = t >> 5;
    const int wm   = wid >> 2;     // 0..3: i-subtile of 16
    const int wn   = wid & 3;      // 0..3: d-subtile of 32
    const int b    = blockIdx.x >> 3;
    const int i0   = (blockIdx.x & 7) * 64;

    float acc[3][4][4];
#pragma unroll
    for (int c = 0; c < 3; ++c)
#pragma unroll
        for (int nt = 0; nt < 4; ++nt)
#pragma unroll
            for (int q = 0; q < 4; ++q) acc[c][nt][q] = 0.0f;

    const uint32_t a_lane = (uint32_t)((wm * 16 + (lane & 15)) * SM_ROW + (lane >> 4) * 16);
    uint32_t b_lane[2];
#pragma unroll
    for (int q = 0; q < 2; ++q) {
        int n = wn * 32 + q * 16 + (lane & 7) + ((lane >> 4) & 1) * 8;
        b_lane[q] = (uint32_t)(B_BASE + n * SM_ROW + ((lane >> 3) & 1) * 16);
    }

    // ---- cp.async issue helpers (each thread owns fixed chunk set)
    auto issue_EM = [&](int j0) {
        // ev: 64 i rows x 768B = 3072 16B-chunks
#pragma unroll
        for (int p = t; p < 3072; p += 512) {
            int i = p / 48, q = p - i * 48;
            const char* src = (const char*)ev
                + ((size_t)((b * 512 + i0 + i) * 512 + j0) * 12) + q * 16;
            CP_ASYNC16(smem_base + RAW_EV + i * 768 + q * 16, src);
        }
        // mask: 64 i rows x 256B = 1024 chunks
#pragma unroll
        for (int p = t; p < 1024; p += 512) {
            int i = p >> 4, q = p & 15;
            const char* src = (const char*)mask
                + ((size_t)((b * 512 + i0 + i) * 512 + j0) * 4) + q * 16;
            CP_ASYNC16(smem_base + RAW_MK + i * 256 + q * 16, src);
        }
        CP_COMMIT();
    };
    auto issue_B = [&](int j0) {
        // 2 splits x 128 d rows x 128B = 2048 chunks
#pragma unroll
        for (int p = t; p < 2048; p += 512) {
            int sp = p >> 10, r = p & 1023;
            int d = r >> 3, q = r & 7;
            const char* srcbase = sp ? (const char*)g_hBlo : (const char*)g_hBhi;
            const char* src = srcbase + ((size_t)((b * 128 + d) * 512 + j0) * 2) + q * 16;
            CP_ASYNC16(smem_base + B_BASE + sp * B_S_STRIDE + d * SM_ROW + q * 16, src);
        }
        CP_COMMIT();
    };

    issue_EM(0);       // prologue: EM(0) in flight

    for (int ch = 0; ch < 8; ++ch) {
        const int j0 = ch * 64;
        __syncthreads();            // MMA(ch-1) done -> conv buffers free
        issue_B(j0);                // B(ch): global -> conv B directly
        CP_WAIT(1);                 // own EM(ch) done (B may pend)
        __syncthreads();            // all EM(ch) visible

        // ---- convert A: per-thread blocks of (i, c, 8 consecutive j)
        // 64i x 3c x 8jb = 1536 blocks, 3 per thread. Packed STS.128.
#pragma unroll
        for (int k = 0; k < 3; ++k) {
            int beta = t + k * 512;
            int i  = beta / 24;
            int r  = beta - i * 24;
            int c  = r >> 3;
            int jb = r & 7;
            const float*  evr = (const float*)(smc + RAW_EV + i * 768) + jb * 24 + c;
            const float4* mkr = (const float4*)(smc + RAW_MK + i * 256) + jb * 2;
            float4 m0 = mkr[0], m1 = mkr[1];
            float mv[8] = {m0.x, m0.y, m0.z, m0.w, m1.x, m1.y, m1.z, m1.w};
            uint32_t hi4[4], lo4[4];
#pragma unroll
            for (int p2 = 0; p2 < 4; ++p2) {
                float v0 = evr[(2 * p2)     * 3] * mv[2 * p2];
                float v1 = evr[(2 * p2 + 1) * 3] * mv[2 * p2 + 1];
                uint32_t vb0 = __float_as_uint(v0), vb1 = __float_as_uint(v1);
                uint32_t h0 = vb0 & 0xFFFF0000u, h1 = vb1 & 0xFFFF0000u;
                float l0f = v0 - __uint_as_float(h0);
                float l1f = v1 - __uint_as_float(h1);
                uint16_t l0 = __bfloat16_as_ushort(__float2bfloat16(l0f));
                uint16_t l1 = __bfloat16_as_ushort(__float2bfloat16(l1f));
                hi4[p2] = (h0 >> 16) | (h1 & 0xFFFF0000u);
                lo4[p2] = (uint32_t)l0 | ((uint32_t)l1 << 16);
            }
            char* dst = smc + c * A_C_STRIDE + i * SM_ROW + jb * 16;
            *(uint4*)dst                 = make_uint4(hi4[0], hi4[1], hi4[2], hi4[3]);
            *(uint4*)(dst + A_S_STRIDE)  = make_uint4(lo4[0], lo4[1], lo4[2], lo4[3]);
        }
        __syncthreads();            // ALL convert reads of RAW done before overwrite

        if (ch < 7) { issue_EM(j0 + 64); CP_WAIT(1); }   // EM(ch+1) pends; B done
        else        { CP_WAIT(0); }
        __syncthreads();            // conv A STS + all B visible

        // ---- compute: kb -> pass -> (c, nt); 12 indep MMAs per acc revisit
#pragma unroll
        for (int kb = 0; kb < 4; ++kb) {
            uint32_t afr[3][2][4];
            uint32_t bfr[2][2][4];
#pragma unroll
            for (int c = 0; c < 3; ++c)
#pragma unroll
                for (int s = 0; s < 2; ++s)
                    LDSM_X4(afr[c][s],
                            smem_base + c * A_C_STRIDE + s * A_S_STRIDE + a_lane + kb * 32);
#pragma unroll
            for (int s = 0; s < 2; ++s)
#pragma unroll
                for (int q = 0; q < 2; ++q)
                    LDSM_X4(bfr[s][q], smem_base + b_lane[q] + s * B_S_STRIDE + kb * 32);

#pragma unroll
            for (int pass = 0; pass < 3; ++pass) {
                const int as = (pass == 1) ? 1 : 0;   // lo*hi pass uses A-lo
                const int bs = (pass == 2) ? 1 : 0;   // hi*lo pass uses B-lo
#pragma unroll
                for (int c = 0; c < 3; ++c) {
#pragma unroll
                    for (int nt = 0; nt < 4; ++nt) {
                        uint32_t* bb = bfr[bs][nt >> 1];
                        MMA_BF16(acc[c][nt], afr[c][as],
                                 bb[(nt & 1) * 2], bb[(nt & 1) * 2 + 1]);
                    }
                }
            }
        }
    }

    // ---- epilogue: fragments -> out[b][i][c][d]
    const int r0 = i0 + wm * 16 + (lane >> 2);
    const int dq = wn * 32 + (lane & 3) * 2;
#pragma unroll
    for (int c = 0; c < 3; ++c) {
#pragma unroll
        for (int nt = 0; nt < 4; ++nt) {
            int d = dq + nt * 8;
            size_t o0 = ((size_t)(b * 512 + r0)     * 3 + c) * 128 + d;
            size_t o1 = ((size_t)(b * 512 + r0 + 8) * 3 + c) * 128 + d;
            *(float2*)(out + o0) = make_float2(acc[c][nt][0], acc[c][nt][1]);
            *(float2*)(out + o1) = make_float2(acc[c][nt][2], acc[c][nt][3]);
        }
    }
}

// ---------------------------------------------------------------------------
extern "C" void kernel_launch(void* const* d_in, const int* in_sizes, int n_in,
                              void* d_out, int out_size) {
    const float* s    = (const float*)d_in[0];   // (32,512,128)
    const float* ev   = (const float*)d_in[1];   // (32,512,512,3)
    const float* mask = (const float*)d_in[2];   // (32,512,512,1)
    const float* W1   = (const float*)d_in[3];   // (128,128)
    const float* b1   = (const float*)d_in[4];   // (128,)
    float* out = (float*)d_out;                  // (32,512,3,128)

    const int k1_smem = (128 * 132 + 128 * 33) * (int)sizeof(float)
                      + 128 * 33 * (int)sizeof(uint32_t);   // 101376
    cudaFuncSetAttribute(k1_lin_ln_silu,
                         cudaFuncAttributeMaxDynamicSharedMemorySize, k1_smem);
    cudaFuncSetAttribute(k2_cfconv_mma,
                         cudaFuncAttributeMaxDynamicSharedMemorySize, K2_SMEM);

    k1_lin_ln_silu<<<(BB * NN) / 64, 256, k1_smem>>>(s, W1, b1);
    k2_cfconv_mma<<<BB * 8, 512, K2_SMEM>>>(ev, mask, out);
}